// round 16
// baseline (speedup 1.0000x reference)
#include <cuda_runtime.h>
#include <cuda_fp16.h>
#include <stdint.h>

#define NSEQ 2048

// ---------------- device scratch ----------------
// per (g, sb, step) 4KB block: [n 32][k 64] fp16 (x part)
__device__ unsigned char g_xn[(size_t)2 * 64 * 256 * 4096];
__device__ __half g_wh16[2 * 384 * 192];   // fp16(W), permuted rows rp = w*48+sec*16+jj,
                                           // h-cols at 64+sigma(j)
__device__ float g_bias[2 * 4 * 128];      // [g][{br,bz,bni,bnh}][j]
__device__ float g_hout[2 * NSEQ * 128];

// SMEM layout (gru): W 384x400B = 153600; x double buffer (32x144B = 4608 each);
// h double buffer (32x272B = 8704 each).
#define XBUF_OFF    153600
#define XBUF_STRIDE 144
#define XBUF_SZ     4608
#define HBUF_OFF    162816
#define HBUF_STRIDE 272
#define HBUF_SZ     8704
#define GRU_SMEM    180224

// ---------------- helpers ----------------
__device__ __forceinline__ uint32_t smem_u32(const void* p) {
    uint32_t a;
    asm("{ .reg .u64 t; cvta.to.shared.u64 t, %1; cvt.u32.u64 %0, t; }" : "=r"(a) : "l"(p));
    return a;
}
__device__ __forceinline__ float tanha(float x) {
    float y; asm("tanh.approx.f32 %0, %1;" : "=f"(y) : "f"(x)); return y;
}
__device__ __forceinline__ float siga(float x) { return 0.5f * tanha(0.5f * x) + 0.5f; }
__device__ __forceinline__ uint32_t pack_h2(__half a, __half b) {
    return (uint32_t)__half_as_ushort(a) | ((uint32_t)__half_as_ushort(b) << 16);
}
__device__ __forceinline__ void ldsm4(uint32_t* r, uint32_t addr) {
    asm volatile("ldmatrix.sync.aligned.m8n8.x4.shared.b16 {%0,%1,%2,%3}, [%4];"
        : "=r"(r[0]), "=r"(r[1]), "=r"(r[2]), "=r"(r[3]) : "r"(addr));
}
__device__ __forceinline__ void ldsm2(uint32_t* r, uint32_t addr) {
    asm volatile("ldmatrix.sync.aligned.m8n8.x2.shared.b16 {%0,%1}, [%2];"
        : "=r"(r[0]), "=r"(r[1]) : "r"(addr));
}
__device__ __forceinline__ void mma16816(float* c, const uint32_t* a, const uint32_t* b) {
    asm volatile("mma.sync.aligned.m16n8k16.row.col.f32.f16.f16.f32 "
        "{%0,%1,%2,%3}, {%4,%5,%6,%7}, {%8,%9}, {%0,%1,%2,%3};"
        : "+f"(c[0]), "+f"(c[1]), "+f"(c[2]), "+f"(c[3])
        : "r"(a[0]), "r"(a[1]), "r"(a[2]), "r"(a[3]), "r"(b[0]), "r"(b[1]));
}

// ---------------- prep: fp16 W (permuted) + fused biases ----------------
__global__ void prep_kernel(const float* __restrict__ Wih_t, const float* __restrict__ Whh_t,
                            const float* __restrict__ bih_t, const float* __restrict__ bhh_t,
                            const float* __restrict__ Wih_f, const float* __restrict__ Whh_f,
                            const float* __restrict__ bih_f, const float* __restrict__ bhh_f) {
    int idx = blockIdx.x * blockDim.x + threadIdx.x;
    const int NW = 2 * 384 * 192;
    if (idx < NW) {
        int k  = idx % 192;
        int rp = (idx / 192) % 384;
        int g  = idx / (384 * 192);
        int w = rp / 48, rem = rp % 48, sec = rem / 16, jj = rem % 16;
        int orig = sec * 128 + w * 16 + jj;
        const float* Wih = g ? Wih_f : Wih_t;
        const float* Whh = g ? Whh_f : Whh_t;
        float v;
        if (k < 64) {
            v = Wih[orig * 64 + k];
        } else {
            int kk = k - 64;
            int w2 = kk >> 4, p = kk & 15;
            int u  = (p >> 1) + ((p & 1) << 3);     // inverse sigma
            v = Whh[orig * 128 + w2 * 16 + u];
        }
        g_wh16[idx] = __float2half_rn(v);
    } else if (idx < NW + 256) {
        int t = idx - NW;
        int g = t >> 7, j = t & 127;
        const float* bih = g ? bih_f : bih_t;
        const float* bhh = g ? bhh_f : bhh_t;
        float* dst = &g_bias[g * 512];
        dst[0 * 128 + j] = bih[j] + bhh[j];
        dst[1 * 128 + j] = bih[128 + j] + bhh[128 + j];
        dst[2 * 128 + j] = bih[256 + j];
        dst[3 * 128 + j] = bhh[256 + j];
    }
}

// ---------------- transpose: n-major fp16 x images ----------------
__global__ void transpose_kernel(const float* __restrict__ x) {
    extern __shared__ float slab[];
    const int bx = blockIdx.x;
    const int fb = bx & 7;
    const int tb = (bx >> 3) & 31;
    const int b  = bx >> 8;
    const int f0 = fb * 32, t0 = tb * 8;
    const int tid = threadIdx.x;
#pragma unroll
    for (int i = 0; i < 16; i++) {
        int idx = tid + i * 256;
        int f4 = idx & 7, tt = (idx >> 3) & 7, c = idx >> 6;
        float4 v = ((const float4*)x)[(((size_t)(b * 64 + c) * 256 + t0 + tt) << 6) + (f0 >> 2) + f4];
        float* d = &slab[c * 257 + tt * 32 + f4 * 4];
        d[0] = v.x; d[1] = v.y; d[2] = v.z; d[3] = v.w;
    }
    __syncthreads();
    const int tt = tid >> 5, ff = tid & 31;
    const int t = t0 + tt, f = f0 + ff;
    uint32_t hiw[32];
#pragma unroll
    for (int q = 0; q < 32; q++) {
        float v0 = slab[(2 * q) * 257 + tt * 32 + ff];
        float v1 = slab[(2 * q + 1) * 257 + tt * 32 + ff];
        hiw[q] = pack_h2(__float2half_rn(v0), __float2half_rn(v1));
    }
    {
        unsigned char* dst = g_xn + ((size_t)(0 * 64 + b * 8 + fb) * 256 + t) * 4096 + ff * 128;
#pragma unroll
        for (int q = 0; q < 8; q++) ((uint4*)dst)[q] = *(uint4*)&hiw[q * 4];
    }
    {
        unsigned char* dst = g_xn + ((size_t)(1 * 64 + b * 8 + (t >> 5)) * 256 + f) * 4096 + (t & 31) * 128;
#pragma unroll
        for (int q = 0; q < 8; q++) ((uint4*)dst)[q] = *(uint4*)&hiw[q * 4];
    }
}

// ---------------- no-op (ncu capture steering: keeps gru the profiled launch) ----------------
__global__ void noop_kernel() {}

// ---------------- GRU recurrent kernel (single-phase step; h-part W in regs) ----------------
__global__ void __launch_bounds__(256, 1) gru_kernel() {
    extern __shared__ __align__(16) unsigned char smem[];
    const uint32_t sbase = smem_u32(smem);
    const int g   = blockIdx.x >> 6;
    const int sq  = blockIdx.x & 63;
    const int tid = threadIdx.x;
    const int w   = tid >> 5;
    const int lane = tid & 31;

    // stage W into smem (400B row stride)
    {
        const uint4* src = (const uint4*)(g_wh16 + (size_t)g * 73728);
        for (int i = 0; i < 36; i++) {
            int idx = tid + i * 256;
            int row = idx / 24, u = idx % 24;
            *(uint4*)(smem + row * 400 + u * 16) = src[idx];
        }
    }
    const uint4* xsrc = (const uint4*)(g_xn + ((size_t)(g * 64 + sq) * 256) * 4096);
    // stage x(0) into buf0; zero h buf0 (h_old reads at s=0)
    {
        uint4 v0 = xsrc[tid];
        const uint32_t xo = (tid >> 3) * XBUF_STRIDE + (tid & 7) * 16;
        *(uint4*)(smem + XBUF_OFF + xo) = v0;
        for (int i = tid; i < 544; i += 256)
            *(uint4*)(smem + HBUF_OFF + i * 16) = make_uint4(0, 0, 0, 0);
    }
    const int jw = lane >> 2;
    const float bR0 = g_bias[g * 512 + 0 + w * 16 + jw], bR1 = g_bias[g * 512 + 0 + w * 16 + jw + 8];
    const float bZ0 = g_bias[g * 512 + 128 + w * 16 + jw], bZ1 = g_bias[g * 512 + 128 + w * 16 + jw + 8];
    const float bI0 = g_bias[g * 512 + 256 + w * 16 + jw], bI1 = g_bias[g * 512 + 256 + w * 16 + jw + 8];
    const float bH0 = g_bias[g * 512 + 384 + w * 16 + jw], bH1 = g_bias[g * 512 + 384 + w * 16 + jw + 8];
    __syncthreads();

    // register-resident A fragments for the h-part ONLY (kt 4..11): 96 regs
    const uint32_t aRow = sbase + (uint32_t)(w * 48 + (lane & 15)) * 400 + ((lane >> 4) & 1) * 16;
    uint32_t wfh[3][8][4];
#pragma unroll
    for (int mt = 0; mt < 3; mt++)
#pragma unroll
        for (int kt = 0; kt < 8; kt++)
            ldsm4(wfh[mt][kt], aRow + mt * 6400 + (kt + 4) * 32);

    const uint32_t bCol  = ((lane >> 3) & 1) * 16;
    const uint32_t xRowB = (uint32_t)(lane & 7) * XBUF_STRIDE + bCol;
    const uint32_t hRowB = (uint32_t)(lane & 7) * HBUF_STRIDE + bCol;
    const uint32_t xStO  = (uint32_t)(tid >> 3) * XBUF_STRIDE + (tid & 7) * 16;
    const uint32_t hSlot = (uint32_t)(w * 32 + jw * 4);   // within h row

    for (int s = 0; s < 256; s++) {
        const uint32_t xcurB = sbase + XBUF_OFF + (s & 1) * XBUF_SZ;
        const uint32_t hcurB = sbase + HBUF_OFF + (s & 1) * HBUF_SZ;
        const uint32_t hcurOff = HBUF_OFF + (s & 1) * HBUF_SZ;
        const uint32_t hnxtOff = HBUF_OFF + ((s & 1) ^ 1) * HBUF_SZ;

        // prefetch x(s+1)
        uint4 xv;
        if (s < 255) xv = xsrc[(size_t)(s + 1) * 256 + tid];

        // prefetch h_old pairs from current h buffer (written before last barrier)
        uint32_t hOld[8];
#pragma unroll
        for (int nt = 0; nt < 4; nt++)
#pragma unroll
            for (int q = 0; q < 2; q++) {
                const int n = nt * 8 + (lane & 3) * 2 + q;
                hOld[nt * 2 + q] =
                    *(uint32_t*)(smem + hcurOff + n * HBUF_STRIDE + hSlot);
            }

        float aR[4][4], aZ[4][4], aNI[4][4], aNH[4][4];
#pragma unroll
        for (int nt = 0; nt < 4; nt++) {
            aR[nt][0] = bR0; aR[nt][1] = bR0; aR[nt][2] = bR1; aR[nt][3] = bR1;
            aZ[nt][0] = bZ0; aZ[nt][1] = bZ0; aZ[nt][2] = bZ1; aZ[nt][3] = bZ1;
            aNI[nt][0] = bI0; aNI[nt][1] = bI0; aNI[nt][2] = bI1; aNI[nt][3] = bI1;
            aNH[nt][0] = bH0; aNH[nt][1] = bH0; aNH[nt][2] = bH1; aNH[nt][3] = bH1;
        }

        // x-part (kt 0..3): A streamed from smem, all nt
#pragma unroll
        for (int kt = 0; kt < 4; kt++) {
            uint32_t af0[4], af1[4], af2[4];
            ldsm4(af0, aRow + 0 * 6400 + kt * 32);
            ldsm4(af1, aRow + 1 * 6400 + kt * 32);
            ldsm4(af2, aRow + 2 * 6400 + kt * 32);
#pragma unroll
            for (int nt = 0; nt < 4; nt++) {
                uint32_t bf[2];
                ldsm2(bf, xcurB + xRowB + nt * (8 * XBUF_STRIDE) + kt * 32);
                mma16816(aR[nt],  af0, bf);
                mma16816(aZ[nt],  af1, bf);
                mma16816(aNI[nt], af2, bf);
            }
        }
        // h-part (kt 4..11): A from registers, all nt; skip at s=0 (h=0)
        if (s > 0) {
#pragma unroll
            for (int kt = 0; kt < 8; kt++) {
#pragma unroll
                for (int nt = 0; nt < 4; nt++) {
                    uint32_t bh[2];
                    ldsm2(bh, hcurB + hRowB + nt * (8 * HBUF_STRIDE) + kt * 32);
                    mma16816(aR[nt],  wfh[0][kt], bh);
                    mma16816(aZ[nt],  wfh[1][kt], bh);
                    mma16816(aNH[nt], wfh[2][kt], bh);
                }
            }
        }

        // single epilogue: gates + h update + publish
#pragma unroll
        for (int nt = 0; nt < 4; nt++) {
#pragma unroll
            for (int q = 0; q < 2; q++) {
                const __half2 hraw = *(__half2*)&hOld[nt * 2 + q];
                const float2 ho = __half22float2(hraw);
                float hv[2];
#pragma unroll
                for (int t2 = 0; t2 < 2; t2++) {
                    const int p = q + t2 * 2;
                    float r  = siga(aR[nt][p]);
                    float z  = siga(aZ[nt][p]);
                    float nn = tanha(fmaf(r, aNH[nt][p], aNI[nt][p]));
                    float hov = t2 ? ho.y : ho.x;
                    float h  = nn + z * (hov - nn);
                    hv[t2] = h;
                    if (s == 255) {
                        const int n = nt * 8 + (lane & 3) * 2 + q;
                        const int j = w * 16 + jw + t2 * 8;
                        g_hout[((size_t)g * NSEQ + sq * 32 + n) * 128 + j] = h;
                    }
                }
                if (s < 255) {
                    const int n = nt * 8 + (lane & 3) * 2 + q;
                    *(uint32_t*)(smem + hnxtOff + n * HBUF_STRIDE + hSlot) =
                        pack_h2(__float2half_rn(hv[0]), __float2half_rn(hv[1]));
                }
            }
        }

        // stage x(s+1) into next buffer
        if (s < 255)
            *(uint4*)(smem + XBUF_OFF + ((s & 1) ^ 1) * XBUF_SZ + xStO) = xv;
        __syncthreads();
    }
}

// ---------------- output projection + broadcast ----------------
__global__ void out_kernel(const float* __restrict__ Wp, const float* __restrict__ bp,
                           float* __restrict__ out) {
    __shared__ float s_vec[128];
    __shared__ float part_s[4][64];
    __shared__ float s_out[64];
    const int bt = blockIdx.x;
    const int b  = bt >> 8;
    const int t  = bt & 255;
    const int tid = threadIdx.x;
    const int nidx = b * 256 + t;

    if (tid < 128)
        s_vec[tid] = g_hout[(size_t)nidx * 128 + tid] +
                     g_hout[((size_t)NSEQ + nidx) * 128 + tid];
    __syncthreads();

    const int c = tid & 63, p = tid >> 6;
    float sum = 0.0f;
#pragma unroll
    for (int h = 0; h < 32; h++)
        sum = fmaf(Wp[c * 128 + p * 32 + h], s_vec[p * 32 + h], sum);
    part_s[p][c] = sum;
    __syncthreads();
    if (tid < 64)
        s_out[tid] = bp[tid] + part_s[0][tid] + part_s[1][tid] + part_s[2][tid] + part_s[3][tid];
    __syncthreads();

    float4* o4 = (float4*)out;
    const size_t base4 = ((size_t)b * 64) * 16384 + (size_t)t * 64;
    for (int e = tid; e < 4096; e += 256) {
        int c2 = e >> 6, f4 = e & 63;
        float v = s_out[c2];
        o4[base4 + (size_t)c2 * 16384 + f4] = make_float4(v, v, v, v);
    }
}

// ---------------- launcher ----------------
extern "C" void kernel_launch(void* const* d_in, const int* in_sizes, int n_in,
                              void* d_out, int out_size) {
    const float* x     = (const float*)d_in[0];
    const float* Wih_t = (const float*)d_in[1];
    const float* Whh_t = (const float*)d_in[2];
    const float* bih_t = (const float*)d_in[3];
    const float* bhh_t = (const float*)d_in[4];
    const float* Wih_f = (const float*)d_in[5];
    const float* Whh_f = (const float*)d_in[6];
    const float* bih_f = (const float*)d_in[7];
    const float* bhh_f = (const float*)d_in[8];
    const float* Wp    = (const float*)d_in[9];
    const float* bp    = (const float*)d_in[10];
    float* out = (float*)d_out;

    cudaFuncSetAttribute(gru_kernel, cudaFuncAttributeMaxDynamicSharedMemorySize, GRU_SMEM);
    cudaFuncSetAttribute(transpose_kernel, cudaFuncAttributeMaxDynamicSharedMemorySize, 65792);

    prep_kernel<<<(2 * 384 * 192 + 256 + 255) / 256, 256>>>(Wih_t, Whh_t, bih_t, bhh_t,
                                                            Wih_f, Whh_f, bih_f, bhh_f);
    transpose_kernel<<<8 * 32 * 8, 256, 65792>>>(x);
    noop_kernel<<<1, 32>>>();
    gru_kernel<<<128, 256, GRU_SMEM>>>();
    out_kernel<<<2048, 256>>>(Wp, bp, out);
}

// round 17
// speedup vs baseline: 1.0945x; 1.0945x over previous
#include <cuda_runtime.h>
#include <cuda_fp16.h>
#include <stdint.h>

#define NSEQ 2048

// ---------------- device scratch ----------------
// per (g, sb, step) 4KB block: [n 32][k 64] fp16 (x part)
__device__ unsigned char g_xn[(size_t)2 * 64 * 256 * 4096];
__device__ __half g_wh16[2 * 384 * 192];   // fp16(W), permuted rows rp = w*48+sec*16+jj,
                                           // h-cols at 64+sigma(j)
__device__ float g_bias[2 * 4 * 128];      // [g][{br,bz,bni,bnh}][j]
__device__ float g_hout[2 * NSEQ * 128];

// SMEM layout (gru): W 384x400B = 153600; x double buffer (32x144B = 4608 each);
// h double buffer (32x272B = 8704 each).
#define XBUF_OFF    153600
#define XBUF_STRIDE 144
#define XBUF_SZ     4608
#define HBUF_OFF    162816
#define HBUF_STRIDE 272
#define HBUF_SZ     8704
#define GRU_SMEM    180224

// ---------------- helpers ----------------
__device__ __forceinline__ uint32_t smem_u32(const void* p) {
    uint32_t a;
    asm("{ .reg .u64 t; cvta.to.shared.u64 t, %1; cvt.u32.u64 %0, t; }" : "=r"(a) : "l"(p));
    return a;
}
__device__ __forceinline__ float tanha(float x) {
    float y; asm("tanh.approx.f32 %0, %1;" : "=f"(y) : "f"(x)); return y;
}
__device__ __forceinline__ float siga(float x) { return 0.5f * tanha(0.5f * x) + 0.5f; }
__device__ __forceinline__ uint32_t pack_h2(__half a, __half b) {
    return (uint32_t)__half_as_ushort(a) | ((uint32_t)__half_as_ushort(b) << 16);
}
__device__ __forceinline__ void ldsm4(uint32_t* r, uint32_t addr) {
    asm volatile("ldmatrix.sync.aligned.m8n8.x4.shared.b16 {%0,%1,%2,%3}, [%4];"
        : "=r"(r[0]), "=r"(r[1]), "=r"(r[2]), "=r"(r[3]) : "r"(addr));
}
__device__ __forceinline__ void ldsm2(uint32_t* r, uint32_t addr) {
    asm volatile("ldmatrix.sync.aligned.m8n8.x2.shared.b16 {%0,%1}, [%2];"
        : "=r"(r[0]), "=r"(r[1]) : "r"(addr));
}
__device__ __forceinline__ void mma16816(float* c, const uint32_t* a, const uint32_t* b) {
    asm volatile("mma.sync.aligned.m16n8k16.row.col.f32.f16.f16.f32 "
        "{%0,%1,%2,%3}, {%4,%5,%6,%7}, {%8,%9}, {%0,%1,%2,%3};"
        : "+f"(c[0]), "+f"(c[1]), "+f"(c[2]), "+f"(c[3])
        : "r"(a[0]), "r"(a[1]), "r"(a[2]), "r"(a[3]), "r"(b[0]), "r"(b[1]));
}

// ---------------- prep: fp16 W (permuted) + fused biases ----------------
__global__ void prep_kernel(const float* __restrict__ Wih_t, const float* __restrict__ Whh_t,
                            const float* __restrict__ bih_t, const float* __restrict__ bhh_t,
                            const float* __restrict__ Wih_f, const float* __restrict__ Whh_f,
                            const float* __restrict__ bih_f, const float* __restrict__ bhh_f) {
    int idx = blockIdx.x * blockDim.x + threadIdx.x;
    const int NW = 2 * 384 * 192;
    if (idx < NW) {
        int k  = idx % 192;
        int rp = (idx / 192) % 384;
        int g  = idx / (384 * 192);
        int w = rp / 48, rem = rp % 48, sec = rem / 16, jj = rem % 16;
        int orig = sec * 128 + w * 16 + jj;
        const float* Wih = g ? Wih_f : Wih_t;
        const float* Whh = g ? Whh_f : Whh_t;
        float v;
        if (k < 64) {
            v = Wih[orig * 64 + k];
        } else {
            int kk = k - 64;
            int w2 = kk >> 4, p = kk & 15;
            int u  = (p >> 1) + ((p & 1) << 3);     // inverse sigma
            v = Whh[orig * 128 + w2 * 16 + u];
        }
        g_wh16[idx] = __float2half_rn(v);
    } else if (idx < NW + 256) {
        int t = idx - NW;
        int g = t >> 7, j = t & 127;
        const float* bih = g ? bih_f : bih_t;
        const float* bhh = g ? bhh_f : bhh_t;
        float* dst = &g_bias[g * 512];
        dst[0 * 128 + j] = bih[j] + bhh[j];
        dst[1 * 128 + j] = bih[128 + j] + bhh[128 + j];
        dst[2 * 128 + j] = bih[256 + j];
        dst[3 * 128 + j] = bhh[256 + j];
    }
}

// ---------------- transpose: n-major fp16 x images ----------------
__global__ void transpose_kernel(const float* __restrict__ x) {
    extern __shared__ float slab[];
    const int bx = blockIdx.x;
    const int fb = bx & 7;
    const int tb = (bx >> 3) & 31;
    const int b  = bx >> 8;
    const int f0 = fb * 32, t0 = tb * 8;
    const int tid = threadIdx.x;
#pragma unroll
    for (int i = 0; i < 16; i++) {
        int idx = tid + i * 256;
        int f4 = idx & 7, tt = (idx >> 3) & 7, c = idx >> 6;
        float4 v = ((const float4*)x)[(((size_t)(b * 64 + c) * 256 + t0 + tt) << 6) + (f0 >> 2) + f4];
        float* d = &slab[c * 257 + tt * 32 + f4 * 4];
        d[0] = v.x; d[1] = v.y; d[2] = v.z; d[3] = v.w;
    }
    __syncthreads();
    const int tt = tid >> 5, ff = tid & 31;
    const int t = t0 + tt, f = f0 + ff;
    uint32_t hiw[32];
#pragma unroll
    for (int q = 0; q < 32; q++) {
        float v0 = slab[(2 * q) * 257 + tt * 32 + ff];
        float v1 = slab[(2 * q + 1) * 257 + tt * 32 + ff];
        hiw[q] = pack_h2(__float2half_rn(v0), __float2half_rn(v1));
    }
    {
        unsigned char* dst = g_xn + ((size_t)(0 * 64 + b * 8 + fb) * 256 + t) * 4096 + ff * 128;
#pragma unroll
        for (int q = 0; q < 8; q++) ((uint4*)dst)[q] = *(uint4*)&hiw[q * 4];
    }
    {
        unsigned char* dst = g_xn + ((size_t)(1 * 64 + b * 8 + (t >> 5)) * 256 + f) * 4096 + (t & 31) * 128;
#pragma unroll
        for (int q = 0; q < 8; q++) ((uint4*)dst)[q] = *(uint4*)&hiw[q * 4];
    }
}

// ---------------- no-op (ncu capture steering: keeps gru the profiled launch) ----------------
__global__ void noop_kernel() {}

// ---------------- GRU recurrent kernel (W-in-regs; chunk-pipelined epilogue) ----------------
__global__ void __launch_bounds__(256, 1) gru_kernel() {
    extern __shared__ __align__(16) unsigned char smem[];
    const uint32_t sbase = smem_u32(smem);
    const int g   = blockIdx.x >> 6;
    const int sq  = blockIdx.x & 63;
    const int tid = threadIdx.x;
    const int w   = tid >> 5;
    const int lane = tid & 31;

    // stage W into smem (400B row stride)
    {
        const uint4* src = (const uint4*)(g_wh16 + (size_t)g * 73728);
        for (int i = 0; i < 36; i++) {
            int idx = tid + i * 256;
            int row = idx / 24, u = idx % 24;
            *(uint4*)(smem + row * 400 + u * 16) = src[idx];
        }
    }
    const uint4* xsrc = (const uint4*)(g_xn + ((size_t)(g * 64 + sq) * 256) * 4096);
    // stage x(0) into buf0
    {
        uint4 v0 = xsrc[tid];
        const uint32_t xo = (tid >> 3) * XBUF_STRIDE + (tid & 7) * 16;
        *(uint4*)(smem + XBUF_OFF + xo) = v0;
    }
    const int jw = lane >> 2;
    const float bR0 = g_bias[g * 512 + 0 + w * 16 + jw], bR1 = g_bias[g * 512 + 0 + w * 16 + jw + 8];
    const float bZ0 = g_bias[g * 512 + 128 + w * 16 + jw], bZ1 = g_bias[g * 512 + 128 + w * 16 + jw + 8];
    const float bI0 = g_bias[g * 512 + 256 + w * 16 + jw], bI1 = g_bias[g * 512 + 256 + w * 16 + jw + 8];
    const float bH0 = g_bias[g * 512 + 384 + w * 16 + jw], bH1 = g_bias[g * 512 + 384 + w * 16 + jw + 8];
    __syncthreads();

    // load ALL A fragments once (weights stay in registers for the whole recurrence)
    const uint32_t aRow = sbase + (uint32_t)(w * 48 + (lane & 15)) * 400 + ((lane >> 4) & 1) * 16;
    uint32_t wf[3][12][4];
#pragma unroll
    for (int mt = 0; mt < 3; mt++)
#pragma unroll
        for (int kt = 0; kt < 12; kt++)
            ldsm4(wf[mt][kt], aRow + mt * 6400 + kt * 32);

    const uint32_t bCol  = ((lane >> 3) & 1) * 16;
    const uint32_t xRowB = (uint32_t)(lane & 7) * XBUF_STRIDE + bCol;
    const uint32_t hRowB = (uint32_t)(lane & 7) * HBUF_STRIDE + bCol;
    const uint32_t xStO  = (uint32_t)(tid >> 3) * XBUF_STRIDE + (tid & 7) * 16;
    const uint32_t hSlot = (uint32_t)(w * 32 + jw * 4);

    float hold[16];
#pragma unroll
    for (int i = 0; i < 16; i++) hold[i] = 0.0f;

    for (int s = 0; s < 256; s++) {
        const uint32_t xcur = sbase + XBUF_OFF + (s & 1) * XBUF_SZ;
        const uint32_t hcur = sbase + HBUF_OFF + (s & 1) * HBUF_SZ;
        const uint32_t hnxtOff = HBUF_OFF + ((s & 1) ^ 1) * HBUF_SZ;

        // prefetch x(s+1)
        uint4 xv;
        if (s < 255) xv = xsrc[(size_t)(s + 1) * 256 + tid];

        float aR[4][4], aZ[4][4], aNI[4][4], aNH[4][4];

        // 4-chunk software pipeline over nt: epilogue(c-1) issues after mma(c),
        // so its MUFUs fill the issue gaps while the tensor pipe stays fed.
#pragma unroll
        for (int c = 0; c < 5; c++) {
            if (c < 4) {
                const int nt = c;
                aR[nt][0] = bR0; aR[nt][1] = bR0; aR[nt][2] = bR1; aR[nt][3] = bR1;
                aZ[nt][0] = bZ0; aZ[nt][1] = bZ0; aZ[nt][2] = bZ1; aZ[nt][3] = bZ1;
                aNI[nt][0] = bI0; aNI[nt][1] = bI0; aNI[nt][2] = bI1; aNI[nt][3] = bI1;
                aNH[nt][0] = bH0; aNH[nt][1] = bH0; aNH[nt][2] = bH1; aNH[nt][3] = bH1;
                // x-part (kt 0..3)
#pragma unroll
                for (int kt = 0; kt < 4; kt++) {
                    uint32_t bf[2];
                    ldsm2(bf, xcur + xRowB + nt * (8 * XBUF_STRIDE) + kt * 32);
                    mma16816(aR[nt],  wf[0][kt], bf);
                    mma16816(aZ[nt],  wf[1][kt], bf);
                    mma16816(aNI[nt], wf[2][kt], bf);
                }
                // h-part (kt 4..11), skip at s=0 (h=0)
                if (s > 0) {
#pragma unroll
                    for (int kt = 4; kt < 12; kt++) {
                        uint32_t bh[2];
                        ldsm2(bh, hcur + hRowB + nt * (8 * HBUF_STRIDE) + (kt - 4) * 32);
                        mma16816(aR[nt],  wf[0][kt], bh);
                        mma16816(aZ[nt],  wf[1][kt], bh);
                        mma16816(aNH[nt], wf[2][kt], bh);
                    }
                }
            }
            if (c >= 1) {
                const int nt = c - 1;
#pragma unroll
                for (int q = 0; q < 2; q++) {
                    float hv[2];
#pragma unroll
                    for (int t2 = 0; t2 < 2; t2++) {
                        const int p = q + t2 * 2;
                        const int idx = nt * 4 + p;
                        float r  = siga(aR[nt][p]);
                        float z  = siga(aZ[nt][p]);
                        float nn = tanha(fmaf(r, aNH[nt][p], aNI[nt][p]));
                        float h  = nn + z * (hold[idx] - nn);
                        hold[idx] = h;
                        hv[t2] = h;
                        if (s == 255) {
                            const int n = nt * 8 + (lane & 3) * 2 + q;
                            const int j = w * 16 + jw + t2 * 8;
                            g_hout[((size_t)g * NSEQ + sq * 32 + n) * 128 + j] = h;
                        }
                    }
                    if (s < 255) {
                        const int n = nt * 8 + (lane & 3) * 2 + q;
                        *(uint32_t*)(smem + hnxtOff + n * HBUF_STRIDE + hSlot) =
                            pack_h2(__float2half_rn(hv[0]), __float2half_rn(hv[1]));
                    }
                }
            }
        }

        // stage x(s+1) into next buffer
        if (s < 255)
            *(uint4*)(smem + XBUF_OFF + ((s & 1) ^ 1) * XBUF_SZ + xStO) = xv;
        __syncthreads();
    }
}

// ---------------- output projection + broadcast ----------------
__global__ void out_kernel(const float* __restrict__ Wp, const float* __restrict__ bp,
                           float* __restrict__ out) {
    __shared__ float s_vec[128];
    __shared__ float part_s[4][64];
    __shared__ float s_out[64];
    const int bt = blockIdx.x;
    const int b  = bt >> 8;
    const int t  = bt & 255;
    const int tid = threadIdx.x;
    const int nidx = b * 256 + t;

    if (tid < 128)
        s_vec[tid] = g_hout[(size_t)nidx * 128 + tid] +
                     g_hout[((size_t)NSEQ + nidx) * 128 + tid];
    __syncthreads();

    const int c = tid & 63, p = tid >> 6;
    float sum = 0.0f;
#pragma unroll
    for (int h = 0; h < 32; h++)
        sum = fmaf(Wp[c * 128 + p * 32 + h], s_vec[p * 32 + h], sum);
    part_s[p][c] = sum;
    __syncthreads();
    if (tid < 64)
        s_out[tid] = bp[tid] + part_s[0][tid] + part_s[1][tid] + part_s[2][tid] + part_s[3][tid];
    __syncthreads();

    float4* o4 = (float4*)out;
    const size_t base4 = ((size_t)b * 64) * 16384 + (size_t)t * 64;
    for (int e = tid; e < 4096; e += 256) {
        int c2 = e >> 6, f4 = e & 63;
        float v = s_out[c2];
        o4[base4 + (size_t)c2 * 16384 + f4] = make_float4(v, v, v, v);
    }
}

// ---------------- launcher ----------------
extern "C" void kernel_launch(void* const* d_in, const int* in_sizes, int n_in,
                              void* d_out, int out_size) {
    const float* x     = (const float*)d_in[0];
    const float* Wih_t = (const float*)d_in[1];
    const float* Whh_t = (const float*)d_in[2];
    const float* bih_t = (const float*)d_in[3];
    const float* bhh_t = (const float*)d_in[4];
    const float* Wih_f = (const float*)d_in[5];
    const float* Whh_f = (const float*)d_in[6];
    const float* bih_f = (const float*)d_in[7];
    const float* bhh_f = (const float*)d_in[8];
    const float* Wp    = (const float*)d_in[9];
    const float* bp    = (const float*)d_in[10];
    float* out = (float*)d_out;

    cudaFuncSetAttribute(gru_kernel, cudaFuncAttributeMaxDynamicSharedMemorySize, GRU_SMEM);
    cudaFuncSetAttribute(transpose_kernel, cudaFuncAttributeMaxDynamicSharedMemorySize, 65792);

    prep_kernel<<<(2 * 384 * 192 + 256 + 255) / 256, 256>>>(Wih_t, Whh_t, bih_t, bhh_t,
                                                            Wih_f, Whh_f, bih_f, bhh_f);
    transpose_kernel<<<8 * 32 * 8, 256, 65792>>>(x);
    noop_kernel<<<1, 32>>>();
    gru_kernel<<<128, 256, GRU_SMEM>>>();
    out_kernel<<<2048, 256>>>(Wp, bp, out);
}